// round 7
// baseline (speedup 1.0000x reference)
#include <cuda_runtime.h>
#include <cstdint>

typedef unsigned long long u64;

#define N_INP   64
#define N_HID   512
#define BATCH   128
#define SEQ     1024
#define DT_C    0.042f
#define CSZ     8
#define BC      8
#define HS      64
#define THREADS 512
#define HYD_P   20      // hyD row pitch (floats)

struct __align__(16) Smem {
    float4 W[512 * 16];           // 131072 B  h2h[:,slice], slot = g ^ (k&15)
    float  hyD[512 * HYD_P];      //  40960 B  hyD[k*20 + b*2] = (hy[b][k], hy[b][k])
    float  wrecv[CSZ * BC * HS];  //  16384 B  [src][b][kin]
    float4 scratch[8 * 8 * 17];   //  17408 B  pass1 partials, row pitch 17 f4
    float  recF[BC * HS];         //   2048 B  rec[b][h]
};                                 // ~208 KB

__device__ __forceinline__ uint32_t smem_u32(const void* p) {
    uint32_t a;
    asm("{ .reg .u64 t; cvta.to.shared.u64 t, %1; cvt.u32.u64 %0, t; }"
        : "=r"(a) : "l"(p));
    return a;
}
__device__ __forceinline__ uint32_t mapa_u32(uint32_t a, uint32_t r) {
    uint32_t d;
    asm("mapa.shared::cluster.u32 %0, %1, %2;" : "=r"(d) : "r"(a), "r"(r));
    return d;
}
__device__ __forceinline__ void st_cluster_f32(uint32_t a, float v) {
    asm volatile("st.shared::cluster.f32 [%0], %1;" :: "r"(a), "f"(v) : "memory");
}
__device__ __forceinline__ void st_cluster_u64(uint32_t a, u64 v) {
    asm volatile("st.shared::cluster.u64 [%0], %1;" :: "r"(a), "l"(v) : "memory");
}
__device__ __forceinline__ uint32_t ctarank() {
    uint32_t r;
    asm("mov.u32 %0, %%cluster_ctarank;" : "=r"(r));
    return r;
}
__device__ __forceinline__ void fma2(u64& d, u64 a, u64 b) {
    asm("fma.rn.f32x2 %0, %1, %2, %0;" : "+l"(d) : "l"(a), "l"(b));
}
__device__ __forceinline__ float2 unpk(u64 v) {
    float2 f;
    asm("mov.b64 {%0, %1}, %2;" : "=f"(f.x), "=f"(f.y) : "l"(v));
    return f;
}
__device__ __forceinline__ u64 dup_f32(float v) {
    u64 d;
    asm("mov.b64 %0, {%1, %1};" : "=l"(d) : "f"(v));
    return d;
}
// tanh(x) = 1 - 2/(e^{2x}+1), via ex2/rcp approx. ~1e-6 rel err.
__device__ __forceinline__ float ftanh(float x) {
    float e, r;
    asm("ex2.approx.f32 %0, %1;" : "=f"(e) : "f"(x * 2.885390082f));
    asm("rcp.approx.f32 %0, %1;" : "=f"(r) : "f"(e + 1.0f));
    return fmaf(-2.0f, r, 1.0f);
}
#define CLUSTER_SYNC() do { \
    asm volatile("barrier.cluster.arrive.aligned;" ::: "memory"); \
    asm volatile("barrier.cluster.wait.aligned;" ::: "memory"); \
} while (0)

// ===================== prelude: i2h_all = tanh(x @ x2h) -> out ==============
#define PRE_CTAS 512
#define XDP 130
__global__ void __launch_bounds__(512, 1)
i2h_kernel(const float* __restrict__ x, const float* __restrict__ x2h,
           float* __restrict__ out)
{
    extern __shared__ float ps[];
    float* W2 = ps;
    float* xd = ps + 64 * 512;
    const int t = threadIdx.x;

    for (int idx = t; idx < 64 * 512 / 4; idx += 512)
        *reinterpret_cast<float4*>(&W2[idx * 4]) =
            *reinterpret_cast<const float4*>(&x2h[idx * 4]);

    const int hg = t >> 3;
    const int rq = t & 7;
    const long r0 = (long)blockIdx.x * 256;

    for (int tile = 0; tile < 16; ++tile) {
        __syncthreads();
        #pragma unroll
        for (int rr = 0; rr < 2; ++rr) {
            int e = t + rr * 512;
            int row = e >> 6, i = e & 63;
            float v = x[(r0 + tile * 16 + row) * 64 + i];
            *reinterpret_cast<float2*>(&xd[row * XDP + i * 2]) = make_float2(v, v);
        }
        __syncthreads();

        u64 acc[2][4];
        #pragma unroll
        for (int a = 0; a < 2; ++a)
            #pragma unroll
            for (int b = 0; b < 4; ++b) acc[a][b] = 0ull;

        const float* xe_p = &xd[(rq * 2 + 0) * XDP];
        const float* xo_p = &xd[(rq * 2 + 1) * XDP];
        #pragma unroll 8
        for (int i = 0; i < 64; ++i) {
            ulonglong2 wA = *reinterpret_cast<const ulonglong2*>(&W2[i * 512 + hg * 8]);
            ulonglong2 wB = *reinterpret_cast<const ulonglong2*>(&W2[i * 512 + hg * 8 + 4]);
            u64 xe = *reinterpret_cast<const u64*>(&xe_p[i * 2]);
            u64 xo = *reinterpret_cast<const u64*>(&xo_p[i * 2]);
            fma2(acc[0][0], wA.x, xe); fma2(acc[0][1], wA.y, xe);
            fma2(acc[0][2], wB.x, xe); fma2(acc[0][3], wB.y, xe);
            fma2(acc[1][0], wA.x, xo); fma2(acc[1][1], wA.y, xo);
            fma2(acc[1][2], wB.x, xo); fma2(acc[1][3], wB.y, xo);
        }
        #pragma unroll
        for (int rr = 0; rr < 2; ++rr) {
            long row = r0 + tile * 16 + rq * 2 + rr;
            float4 o0, o1; float2 f;
            f = unpk(acc[rr][0]); o0.x = ftanh(f.x); o0.y = ftanh(f.y);
            f = unpk(acc[rr][1]); o0.z = ftanh(f.x); o0.w = ftanh(f.y);
            f = unpk(acc[rr][2]); o1.x = ftanh(f.x); o1.y = ftanh(f.y);
            f = unpk(acc[rr][3]); o1.z = ftanh(f.x); o1.w = ftanh(f.y);
            *reinterpret_cast<float4*>(&out[row * 512 + hg * 8])     = o0;
            *reinterpret_cast<float4*>(&out[row * 512 + hg * 8 + 4]) = o1;
        }
    }
}

// ===================== main recurrence =====================================
__global__ void __launch_bounds__(THREADS, 1) __cluster_dims__(CSZ, 1, 1)
piron_kernel(const float* __restrict__ h2h,
             const float* __restrict__ bias,
             const float* __restrict__ gamma,
             const float* __restrict__ eps,
             float* outp,
             int out_size)
{
    extern __shared__ Smem smem[];
    Smem& S = smem[0];
    const int      t       = threadIdx.x;
    const uint32_t rank    = ctarank();
    const int      cluster = blockIdx.x / CSZ;
    const int      h0      = (int)rank * HS;

    // ---- init ----
    for (int idx = t; idx < 512 * 16; idx += THREADS) {
        int k = idx >> 4, gq = idx & 15;
        float4 v = *reinterpret_cast<const float4*>(h2h + (size_t)k * N_HID + h0 + gq * 4);
        S.W[(k << 4) | (gq ^ (k & 15))] = v;
    }
    for (int idx = t; idx < 512 * HYD_P; idx += THREADS) S.hyD[idx] = 0.f;
    __syncthreads();
    CLUSTER_SYNC();

    // ---- thread roles ----
    const int ks = t >> 6;               // pass1 k-split
    const int gh = (t >> 5) & 1;
    const int bp = (t >> 3) & 3;
    const int g  = gh * 8 + (t & 7);
    const int eb  = t >> 6;              // owned batch (update/E)
    const int ekk = t & 63;              // owned k within slice

    // ---- per-thread persistent state (registers) ----
    const float bs = bias[h0 + ekk];
    const float gm = gamma[h0 + ekk];
    const float ep = eps[h0 + ekk];
    float hy = 0.f, hz = 0.f;

    // D scatter: whole warp targets peer (t>>6); one mapa'd base, +b*256B.
    const uint32_t wr_base = mapa_u32(
        smem_u32(&S.wrecv[(int)rank * 512 + ekk]), (uint32_t)(t >> 6));
    // E broadcast target (local address; mapa per peer in-loop)
    const uint32_t hyd_loc = smem_u32(&S.hyD[(h0 + ekk) * HYD_P + eb * 2]);
    // out pointer for this thread's (b, h) element
    float* po = outp + (size_t)(cluster * BC + eb) * SEQ * N_HID + h0 + ekk;

    const float* scF = reinterpret_cast<const float*>(S.scratch);

    for (int step = 0; step < SEQ; ++step) {
        // i2h for this step (written by prelude; overwritten by hy below)
        float i2 = po[(size_t)step * N_HID];

        // ---- B: pass1 partials over 64-k split ----
        u64 a00 = 0, a01 = 0, a10 = 0, a11 = 0;
        {
            const float4* Wp = S.W + (ks << 10);
            const float*  Hp = S.hyD + ks * (64 * HYD_P) + bp * 4;
            #pragma unroll 8
            for (int j = 0; j < 64; ++j) {
                ulonglong2 w2 = *reinterpret_cast<const ulonglong2*>(
                    Wp + (j << 4) + (g ^ (j & 15)));
                ulonglong2 h2 = *reinterpret_cast<const ulonglong2*>(Hp + j * HYD_P);
                fma2(a00, w2.x, h2.x); fma2(a01, w2.y, h2.x);
                fma2(a10, w2.x, h2.y); fma2(a11, w2.y, h2.y);
            }
        }
        {
            int row = (ks * 8 + bp * 2) * 17 + g;
            ulonglong2 s;
            s.x = a00; s.y = a01;
            *reinterpret_cast<ulonglong2*>(&S.scratch[row]) = s;
            s.x = a10; s.y = a11;
            *reinterpret_cast<ulonglong2*>(&S.scratch[row + 17]) = s;
        }
        __syncthreads();

        // ---- C: reduce 8 splits + bias + tanh -> recF ----
        {
            float v = bs;
            #pragma unroll
            for (int s = 0; s < 8; ++s) v += scF[(s * 8 + eb) * 68 + ekk];
            S.recF[t] = ftanh(v);
        }
        __syncthreads();

        // ---- D: pass2, thread per k; scatter to owner CTA ----
        {
            const float4* Wr = S.W + (t << 4);
            const int swz = t & 15;
            u64 acc[8];
            #pragma unroll
            for (int b = 0; b < 8; ++b) acc[b] = 0ull;
            #pragma unroll 4
            for (int gg = 0; gg < 16; ++gg) {
                ulonglong2 w2 = *reinterpret_cast<const ulonglong2*>(Wr + (gg ^ swz));
                #pragma unroll
                for (int b = 0; b < 8; ++b) {
                    ulonglong2 r2 = *reinterpret_cast<const ulonglong2*>(
                        &S.recF[b * 64 + gg * 4]);
                    fma2(acc[b], w2.x, r2.x);
                    fma2(acc[b], w2.y, r2.y);
                }
            }
            #pragma unroll
            for (int b = 0; b < 8; ++b) {
                float2 f = unpk(acc[b]);
                st_cluster_f32(wr_base + (uint32_t)(b * 256), f.x + f.y);
            }
        }
        CLUSTER_SYNC();   // scatter complete everywhere

        // ---- E: reduce partials, update state, emit, broadcast into hyD ----
        {
            float w = 0.f;
            #pragma unroll
            for (int src = 0; src < 8; ++src) w += S.wrecv[src * 512 + t];
            hz += DT_C * (i2 - w - gm * hy - ep * hz);
            hy += DT_C * hz;
            po[(size_t)step * N_HID] = hy;
            u64 d = dup_f32(hy);
            #pragma unroll
            for (uint32_t p = 0; p < CSZ; ++p)
                st_cluster_u64(mapa_u32(hyd_loc, p), d);
        }
        CLUSTER_SYNC();   // hyD consistent before next step
    }

    // ---- final hy appended after states ----
    if (out_size >= BATCH * SEQ * N_HID + BATCH * N_HID) {
        outp[(size_t)BATCH * SEQ * N_HID +
             (size_t)(cluster * BC + eb) * N_HID + h0 + ekk] = hy;
    }
}

extern "C" void kernel_launch(void* const* d_in, const int* in_sizes, int n_in,
                              void* d_out, int out_size) {
    (void)in_sizes; (void)n_in;
    const float* x     = (const float*)d_in[0];
    const float* x2h   = (const float*)d_in[1];
    const float* h2h   = (const float*)d_in[2];
    const float* bias  = (const float*)d_in[3];
    const float* gamma = (const float*)d_in[4];
    const float* eps   = (const float*)d_in[5];
    float* out = (float*)d_out;

    const int pre_smem = (64 * 512 + 16 * XDP) * 4;
    cudaFuncSetAttribute(i2h_kernel,
                         cudaFuncAttributeMaxDynamicSharedMemorySize, pre_smem);
    cudaFuncSetAttribute(piron_kernel,
                         cudaFuncAttributeMaxDynamicSharedMemorySize, (int)sizeof(Smem));

    i2h_kernel<<<PRE_CTAS, 512, pre_smem>>>(x, x2h, out);
    piron_kernel<<<(BATCH / BC) * CSZ, THREADS, sizeof(Smem)>>>(
        h2h, bias, gamma, eps, out, out_size);
}

// round 9
// speedup vs baseline: 1.5356x; 1.5356x over previous
#include <cuda_runtime.h>
#include <cstdint>

typedef unsigned long long u64;

#define N_INP   64
#define N_HID   512
#define BATCH   128
#define SEQ     1024
#define DT_C    0.042f
#define CSZ     8
#define BC      8
#define HS      64
#define THREADS 256
#define HYF_P   516     // hy_full row pitch (floats)
#define HYD_P   20      // hyD row pitch (floats), bank-staggered

struct __align__(16) Smem {
    float4 W[512 * 16];           // 131072 B  h2h[:,slice], slot = g ^ (k&15)
    float  hyD[512 * HYD_P];      //  40960 B  [k*20 + b*2] = dup pair of hy[b][k]
    float  hy_full[BC * HYF_P];   //  16512 B  all-gathered hy, [b][k]
    float  wrecv[CSZ * BC * HS];  //  16384 B  [src][b][kin]
    float4 scratch[4 * 8 * 16];   //   8192 B  pass1 partials [ks][b][g]
    float  recF[BC * HS];         //   2048 B  rec[b][h]
};                                 // ~215 KB

__device__ __forceinline__ uint32_t smem_u32(const void* p) {
    uint32_t a;
    asm("{ .reg .u64 t; cvta.to.shared.u64 t, %1; cvt.u32.u64 %0, t; }"
        : "=r"(a) : "l"(p));
    return a;
}
__device__ __forceinline__ uint32_t mapa_u32(uint32_t a, uint32_t r) {
    uint32_t d;
    asm("mapa.shared::cluster.u32 %0, %1, %2;" : "=r"(d) : "r"(a), "r"(r));
    return d;
}
__device__ __forceinline__ void st_cluster_f32(uint32_t a, float v) {
    asm volatile("st.shared::cluster.f32 [%0], %1;" :: "r"(a), "f"(v) : "memory");
}
__device__ __forceinline__ void st_cluster_u64(uint32_t a, u64 v) {
    asm volatile("st.shared::cluster.u64 [%0], %1;" :: "r"(a), "l"(v) : "memory");
}
__device__ __forceinline__ uint32_t ctarank() {
    uint32_t r;
    asm("mov.u32 %0, %%cluster_ctarank;" : "=r"(r));
    return r;
}
__device__ __forceinline__ void fma2(u64& d, u64 a, u64 b) {
    asm("fma.rn.f32x2 %0, %1, %2, %0;" : "+l"(d) : "l"(a), "l"(b));
}
__device__ __forceinline__ float2 unpk(u64 v) {
    float2 f;
    asm("mov.b64 {%0, %1}, %2;" : "=f"(f.x), "=f"(f.y) : "l"(v));
    return f;
}
__device__ __forceinline__ u64 pack2(float a, float b) {
    u64 d;
    asm("mov.b64 %0, {%1, %2};" : "=l"(d) : "f"(a), "f"(b));
    return d;
}
// tanh(x) = 1 - 2/(e^{2x}+1), ex2/rcp approx. ~1e-6 rel err.
__device__ __forceinline__ float ftanh(float x) {
    float e, r;
    asm("ex2.approx.f32 %0, %1;" : "=f"(e) : "f"(x * 2.885390082f));
    asm("rcp.approx.f32 %0, %1;" : "=f"(r) : "f"(e + 1.0f));
    return fmaf(-2.0f, r, 1.0f);
}
#define CLUSTER_SYNC() do { \
    asm volatile("barrier.cluster.arrive.aligned;" ::: "memory"); \
    asm volatile("barrier.cluster.wait.aligned;" ::: "memory"); \
} while (0)

// ===================== prelude: i2h_all = tanh(x @ x2h) -> out ==============
#define PRE_CTAS 512
#define XDP 130
__global__ void __launch_bounds__(512, 1)
i2h_kernel(const float* __restrict__ x, const float* __restrict__ x2h,
           float* __restrict__ out)
{
    extern __shared__ float ps[];
    float* W2 = ps;
    float* xd = ps + 64 * 512;
    const int t = threadIdx.x;

    for (int idx = t; idx < 64 * 512 / 4; idx += 512)
        *reinterpret_cast<float4*>(&W2[idx * 4]) =
            *reinterpret_cast<const float4*>(&x2h[idx * 4]);

    const int hg = t >> 3;
    const int rq = t & 7;
    const long r0 = (long)blockIdx.x * 256;

    for (int tile = 0; tile < 16; ++tile) {
        __syncthreads();
        #pragma unroll
        for (int rr = 0; rr < 2; ++rr) {
            int e = t + rr * 512;
            int row = e >> 6, i = e & 63;
            float v = x[(r0 + tile * 16 + row) * 64 + i];
            *reinterpret_cast<float2*>(&xd[row * XDP + i * 2]) = make_float2(v, v);
        }
        __syncthreads();

        u64 acc[2][4];
        #pragma unroll
        for (int a = 0; a < 2; ++a)
            #pragma unroll
            for (int b = 0; b < 4; ++b) acc[a][b] = 0ull;

        const float* xe_p = &xd[(rq * 2 + 0) * XDP];
        const float* xo_p = &xd[(rq * 2 + 1) * XDP];
        #pragma unroll 8
        for (int i = 0; i < 64; ++i) {
            ulonglong2 wA = *reinterpret_cast<const ulonglong2*>(&W2[i * 512 + hg * 8]);
            ulonglong2 wB = *reinterpret_cast<const ulonglong2*>(&W2[i * 512 + hg * 8 + 4]);
            u64 xe = *reinterpret_cast<const u64*>(&xe_p[i * 2]);
            u64 xo = *reinterpret_cast<const u64*>(&xo_p[i * 2]);
            fma2(acc[0][0], wA.x, xe); fma2(acc[0][1], wA.y, xe);
            fma2(acc[0][2], wB.x, xe); fma2(acc[0][3], wB.y, xe);
            fma2(acc[1][0], wA.x, xo); fma2(acc[1][1], wA.y, xo);
            fma2(acc[1][2], wB.x, xo); fma2(acc[1][3], wB.y, xo);
        }
        #pragma unroll
        for (int rr = 0; rr < 2; ++rr) {
            long row = r0 + tile * 16 + rq * 2 + rr;
            float4 o0, o1; float2 f;
            f = unpk(acc[rr][0]); o0.x = ftanh(f.x); o0.y = ftanh(f.y);
            f = unpk(acc[rr][1]); o0.z = ftanh(f.x); o0.w = ftanh(f.y);
            f = unpk(acc[rr][2]); o1.x = ftanh(f.x); o1.y = ftanh(f.y);
            f = unpk(acc[rr][3]); o1.z = ftanh(f.x); o1.w = ftanh(f.y);
            *reinterpret_cast<float4*>(&out[row * 512 + hg * 8])     = o0;
            *reinterpret_cast<float4*>(&out[row * 512 + hg * 8 + 4]) = o1;
        }
    }
}

// ===================== main recurrence =====================================
__global__ void __launch_bounds__(THREADS, 1) __cluster_dims__(CSZ, 1, 1)
piron_kernel(const float* __restrict__ h2h,
             const float* __restrict__ bias,
             const float* __restrict__ gamma,
             const float* __restrict__ eps,
             float* outp,
             int out_size)
{
    extern __shared__ Smem smem[];
    Smem& S = smem[0];
    const int      t       = threadIdx.x;
    const uint32_t rank    = ctarank();
    const int      cluster = blockIdx.x / CSZ;
    const int      h0      = (int)rank * HS;

    // ---- init ----
    for (int idx = t; idx < 512 * 16; idx += THREADS) {
        int k = idx >> 4, gq = idx & 15;
        float4 v = *reinterpret_cast<const float4*>(h2h + (size_t)k * N_HID + h0 + gq * 4);
        S.W[(k << 4) | (gq ^ (k & 15))] = v;
    }
    for (int idx = t; idx < 512 * HYD_P; idx += THREADS) S.hyD[idx] = 0.f;
    for (int idx = t; idx < BC * HYF_P; idx += THREADS) S.hy_full[idx] = 0.f;
    __syncthreads();
    CLUSTER_SYNC();

    // ---- thread roles ----
    // A: tb (batch), tkb (k block of 16)
    const int tb  = t & 7;
    const int tkb = t >> 3;
    // B: g (h-quad), bq (batch pair), ks (k split of 128)
    const int g  = t & 15;
    const int bq = (t >> 4) & 3;
    const int ks = t >> 6;
    // C/E: eb (batch), h2 (even h within slice; thread owns h2, h2+1)
    const int eb = t >> 5;
    const int h2 = (t & 31) * 2;

    // ---- persistent per-thread state (registers) ----
    float2 bs = *reinterpret_cast<const float2*>(bias  + h0 + h2);
    float2 gm = *reinterpret_cast<const float2*>(gamma + h0 + h2);
    float2 ep = *reinterpret_cast<const float2*>(eps   + h0 + h2);
    float hy0 = 0.f, hy1 = 0.f, hz0 = 0.f, hz1 = 0.f;

    // D scatter bases: rows k0=t (peer t>>6), k1=t+256 (peer (t>>6)+4); kin = t&63
    const uint32_t sc_loc = smem_u32(&S.wrecv[(int)rank * 512 + (t & 63)]);
    const uint32_t sc0 = mapa_u32(sc_loc, (uint32_t)(t >> 6));
    const uint32_t sc1 = mapa_u32(sc_loc, (uint32_t)(t >> 6) + 4);
    // E broadcast addresses into every CTA's hy_full
    uint32_t hb[CSZ];
    {
        uint32_t loc = smem_u32(&S.hy_full[eb * HYF_P + h0 + h2]);
        #pragma unroll
        for (uint32_t p = 0; p < CSZ; ++p) hb[p] = mapa_u32(loc, p);
    }
    // out pointer for this thread's (b, h-pair)
    float* po = outp + (size_t)(cluster * BC + eb) * SEQ * N_HID + h0 + h2;

    const float* scF = reinterpret_cast<const float*>(S.scratch);

    for (int step = 0; step < SEQ; ++step) {
        // ---- A: hy_full -> hyD (transpose + dup) ----
        {
            int kk0 = tkb * 16;
            #pragma unroll
            for (int j = 0; j < 4; ++j) {
                float4 v = *reinterpret_cast<const float4*>(
                    &S.hy_full[tb * HYF_P + kk0 + j * 4]);
                int k = kk0 + j * 4;
                *reinterpret_cast<float2*>(&S.hyD[(k + 0) * HYD_P + tb * 2]) = make_float2(v.x, v.x);
                *reinterpret_cast<float2*>(&S.hyD[(k + 1) * HYD_P + tb * 2]) = make_float2(v.y, v.y);
                *reinterpret_cast<float2*>(&S.hyD[(k + 2) * HYD_P + tb * 2]) = make_float2(v.z, v.z);
                *reinterpret_cast<float2*>(&S.hyD[(k + 3) * HYD_P + tb * 2]) = make_float2(v.w, v.w);
            }
        }
        __syncthreads();

        // ---- B: pass1 partials (i2h prefetched into regs, used in E) ----
        float2 i2 = *reinterpret_cast<const float2*>(po + (size_t)step * N_HID);
        {
            const float4* Wp = S.W + (ks << 11);                       // ks*128 rows
            const float*  Hp = S.hyD + ks * 128 * HYD_P + bq * 4;      // dup pairs
            u64 a00 = 0, a01 = 0, a10 = 0, a11 = 0;
            #pragma unroll 8
            for (int j = 0; j < 128; ++j) {
                ulonglong2 w2 = *reinterpret_cast<const ulonglong2*>(
                    Wp + (j << 4) + (g ^ (j & 15)));
                ulonglong2 hv = *reinterpret_cast<const ulonglong2*>(Hp + j * HYD_P);
                fma2(a00, w2.x, hv.x); fma2(a01, w2.y, hv.x);
                fma2(a10, w2.x, hv.y); fma2(a11, w2.y, hv.y);
            }
            ulonglong2 s;
            int row = (ks * 8 + bq * 2) * 16 + g;
            s.x = a00; s.y = a01;
            *reinterpret_cast<ulonglong2*>(&S.scratch[row]) = s;
            s.x = a10; s.y = a11;
            *reinterpret_cast<ulonglong2*>(&S.scratch[row + 16]) = s;
        }
        __syncthreads();

        // ---- C: reduce 4 k-splits + bias + tanh -> recF (f2 per thread) ----
        {
            float2 v = bs;
            #pragma unroll
            for (int s = 0; s < 4; ++s) {
                float2 u = *reinterpret_cast<const float2*>(
                    &scF[(s * 8 + eb) * 64 + h2]);
                v.x += u.x; v.y += u.y;
            }
            *reinterpret_cast<float2*>(&S.recF[eb * 64 + h2]) =
                make_float2(ftanh(v.x), ftanh(v.y));
        }
        __syncthreads();

        // ---- D: pass2, thread owns rows k0=t, k1=t+256 for all 8 b ----
        {
            const float4* W0 = S.W + (t << 4);
            const float4* W1 = S.W + ((t + 256) << 4);
            const int swz = t & 15;
            u64 acc0[8], acc1[8];
            #pragma unroll
            for (int b = 0; b < 8; ++b) { acc0[b] = 0ull; acc1[b] = 0ull; }
            #pragma unroll 4
            for (int gg = 0; gg < 16; ++gg) {
                ulonglong2 w0 = *reinterpret_cast<const ulonglong2*>(W0 + (gg ^ swz));
                ulonglong2 w1 = *reinterpret_cast<const ulonglong2*>(W1 + (gg ^ swz));
                #pragma unroll
                for (int b = 0; b < 8; ++b) {
                    ulonglong2 r2 = *reinterpret_cast<const ulonglong2*>(
                        &S.recF[b * 64 + gg * 4]);
                    fma2(acc0[b], w0.x, r2.x); fma2(acc0[b], w0.y, r2.y);
                    fma2(acc1[b], w1.x, r2.x); fma2(acc1[b], w1.y, r2.y);
                }
            }
            #pragma unroll
            for (int b = 0; b < 8; ++b) {
                float2 f0 = unpk(acc0[b]);
                float2 f1 = unpk(acc1[b]);
                st_cluster_f32(sc0 + (uint32_t)(b * 256), f0.x + f0.y);
                st_cluster_f32(sc1 + (uint32_t)(b * 256), f1.x + f1.y);
            }
        }
        CLUSTER_SYNC();   // scatter complete everywhere

        // ---- E: reduce 8 partials, update state, emit, all-gather hy ----
        {
            float2 w = make_float2(0.f, 0.f);
            #pragma unroll
            for (int src = 0; src < 8; ++src) {
                float2 u = *reinterpret_cast<const float2*>(
                    &S.wrecv[src * 512 + eb * 64 + h2]);
                w.x += u.x; w.y += u.y;
            }
            hz0 += DT_C * (i2.x - w.x - gm.x * hy0 - ep.x * hz0);
            hz1 += DT_C * (i2.y - w.y - gm.y * hy1 - ep.y * hz1);
            hy0 += DT_C * hz0;
            hy1 += DT_C * hz1;
            *reinterpret_cast<float2*>(po + (size_t)step * N_HID) =
                make_float2(hy0, hy1);
            u64 d = pack2(hy0, hy1);
            #pragma unroll
            for (uint32_t p = 0; p < CSZ; ++p) st_cluster_u64(hb[p], d);
        }
        CLUSTER_SYNC();   // hy_full consistent before next step
    }

    // ---- final hy appended after states ----
    if (out_size >= BATCH * SEQ * N_HID + BATCH * N_HID) {
        *reinterpret_cast<float2*>(
            outp + (size_t)BATCH * SEQ * N_HID +
            (size_t)(cluster * BC + eb) * N_HID + h0 + h2) = make_float2(hy0, hy1);
    }
}

extern "C" void kernel_launch(void* const* d_in, const int* in_sizes, int n_in,
                              void* d_out, int out_size) {
    (void)in_sizes; (void)n_in;
    const float* x     = (const float*)d_in[0];
    const float* x2h   = (const float*)d_in[1];
    const float* h2h   = (const float*)d_in[2];
    const float* bias  = (const float*)d_in[3];
    const float* gamma = (const float*)d_in[4];
    const float* eps   = (const float*)d_in[5];
    float* out = (float*)d_out;

    const int pre_smem = (64 * 512 + 16 * XDP) * 4;
    cudaFuncSetAttribute(i2h_kernel,
                         cudaFuncAttributeMaxDynamicSharedMemorySize, pre_smem);
    cudaFuncSetAttribute(piron_kernel,
                         cudaFuncAttributeMaxDynamicSharedMemorySize, (int)sizeof(Smem));

    i2h_kernel<<<PRE_CTAS, 512, pre_smem>>>(x, x2h, out);
    piron_kernel<<<(BATCH / BC) * CSZ, THREADS, sizeof(Smem)>>>(
        h2h, bias, gamma, eps, out, out_size);
}